// round 9
// baseline (speedup 1.0000x reference)
#include <cuda_runtime.h>
#include <cstdint>

#define BB 4
#define QQ 1024
#define KKEYS 2048
#define NB 16
#define VD 512
#define CHUNK 256
#define NCHUNK 8
#define ROWS 4            // per block: 2 packed row-pairs, 4 warps per pair
#define CAPH 64           // compaction capacity per half-row
#define TAU 2e-7f

typedef unsigned long long ull;
#define SGN2   0x8000000080000000ULL
#define ONES2  0x3F8000003F800000ULL
#define SC2    0x4380000043800000ULL   // (256.0f, 256.0f) exact 2^8 scale

static __device__ __forceinline__ ull pk2(float a, float b) {
    ull r; asm("mov.b64 %0,{%1,%2};" : "=l"(r) : "f"(a), "f"(b)); return r;
}
static __device__ __forceinline__ void upk2(ull v, float& a, float& b) {
    asm("mov.b64 {%0,%1},%2;" : "=f"(a), "=f"(b) : "l"(v));
}
static __device__ __forceinline__ ull add2(ull a, ull b) {
    ull r; asm("add.rn.f32x2 %0,%1,%2;" : "=l"(r) : "l"(a), "l"(b)); return r;
}
static __device__ __forceinline__ ull mul2(ull a, ull b) {
    ull r; asm("mul.rn.f32x2 %0,%1,%2;" : "=l"(r) : "l"(a), "l"(b)); return r;
}

// ---------------------------------------------------------------------------
// Fused, max-free. 256 thr / 4 rows / block, grid 1024 -> 8192 warps chip-wide
// (2x R8) for latency hiding. Phase A: 4 warps per packed row-pair, 64 keys
// each per chunk. Phase D: 2 warps per row (half the keys each) with per-half
// ballot compaction. Phase E: 2 warps per row (half the V columns each).
// ---------------------------------------------------------------------------
__global__ void __launch_bounds__(256, 5) fused_kernel(
    const float* __restrict__ qbits,
    const float* __restrict__ kbits,
    const float* __restrict__ vals,
    const int*   __restrict__ mask,
    float*       __restrict__ Out,
    float*       __restrict__ W)
{
    __shared__ float skey[CHUNK * 20];     // pad 20 -> conflict-free LDS.128
    __shared__ int   smask[CHUNK];
    __shared__ ull   sqn[2][NB];           // packed negated q bits per row-pair
    __shared__ float ssum[ROWS];
    __shared__ float ssw[ROWS][2][CAPH];   // per-row, per-half compaction
    __shared__ int   ssidx[ROWS][2][CAPH];
    __shared__ int   scnt[ROWS][2];
    __shared__ int   sovf[ROWS];

    const int tid = threadIdx.x;
    const int w   = tid >> 5;              // warp 0..7
    const int kx  = tid & 31;
    const int p   = w >> 2;                // row-pair 0..1
    const int h   = w & 3;                 // key quarter within chunk
    const int b   = blockIdx.x >> 8;       // 256 blocks per batch
    const int qt  = blockIdx.x & 255;
    const int rowA = b * QQ + qt * ROWS + 2 * p;
    const int rowB = rowA + 1;

    if (tid < ROWS) { ssum[tid] = 0.0f; sovf[tid] = 0; }
    if (tid < 2 * NB) {                    // packed negated query bits
        int pp = tid >> 4, bit = tid & 15;
        int rA = b * QQ + qt * ROWS + 2 * pp;
        float qa = qbits[(size_t)rA * NB + bit];
        float qc = qbits[(size_t)(rA + 1) * NB + bit];
        sqn[pp][bit] = pk2(-qa, -qc);
    }

    float* wrA = W + (size_t)rowA * KKEYS;
    float* wrB = W + (size_t)rowB * KKEYS;
    const float4* kbase4 = (const float4*)(kbits + (size_t)b * KKEYS * NB);
    const int*    mbase  = mask + b * KKEYS;

    // ---- Phase A: packed products -> r10 -> W; accumulate packed sums ----
    ull s2 = 0ULL;
    for (int c = 0; c < NCHUNK; c++) {
#pragma unroll
        for (int it = 0; it < 4; it++) {   // stage 256 keys x 16 floats
            int i = tid + it * 256;
            int k = i >> 2, j = i & 3;
            float4 v = kbase4[(size_t)(c * CHUNK + k) * 4 + j];
            *(float4*)&skey[k * 20 + j * 4] = v;
        }
        if (tid < CHUNK) smask[tid] = mbase[c * CHUNK + tid];
        __syncthreads();

        ull prod[2];
#pragma unroll 1
        for (int g = 0; g < 4; g++) {      // bit-group outer: few live q-regs
            const ull q0 = sqn[p][g * 4 + 0];
            const ull q1 = sqn[p][g * 4 + 1];
            const ull q2 = sqn[p][g * 4 + 2];
            const ull q3 = sqn[p][g * 4 + 3];
#pragma unroll
            for (int j = 0; j < 2; j++) {
                const int kl = h * 64 + j * 32 + kx;
                float4 kv = *(const float4*)&skey[kl * 20 + g * 4];
                // t = 1 - |q-k| = 1 + ((k-q) | signbit)
                ull t0 = add2(ONES2, add2(q0, pk2(kv.x, kv.x)) | SGN2);
                ull t1 = add2(ONES2, add2(q1, pk2(kv.y, kv.y)) | SGN2);
                ull t2 = add2(ONES2, add2(q2, pk2(kv.z, kv.z)) | SGN2);
                ull t3 = add2(ONES2, add2(q3, pk2(kv.w, kv.w)) | SGN2);
                ull m  = mul2(mul2(t0, t1), mul2(t2, t3));
                prod[j] = (g == 0) ? m : mul2(prod[j], m);
            }
        }
#pragma unroll
        for (int j = 0; j < 2; j++) {
            const int kl = h * 64 + j * 32 + kx;
            // r10 = (256*p)^10  (exact 2^80 scale; max-free normalization)
            ull r   = mul2(prod[j], SC2);
            ull r2  = mul2(r, r);
            ull r4  = mul2(r2, r2);
            ull r8  = mul2(r4, r4);
            ull r10 = mul2(r8, r2);
            float ra, rb; upk2(r10, ra, rb);
            if (smask[kl] == 0) { ra = 0.0f; rb = 0.0f; }
            const int kg = c * CHUNK + kl;
            wrA[kg] = ra;
            wrB[kg] = rb;
            s2 = add2(s2, pk2(ra, rb));
        }
        __syncthreads();
    }

    // ---- reduce sums: lanes -> warp, then 4 warps per pair via atomics ----
    float sA, sB; upk2(s2, sA, sB);
#pragma unroll
    for (int off = 16; off; off >>= 1) {
        sA += __shfl_xor_sync(0xffffffffu, sA, off);
        sB += __shfl_xor_sync(0xffffffffu, sB, off);
    }
    if (kx == 0) {
        atomicAdd(&ssum[2 * p],     sA);
        atomicAdd(&ssum[2 * p + 1], sB);
    }
    __syncthreads();

    // ---- Phase D: warp w -> row w>>1, key-half w&1. Normalize + compact ----
    const int drow  = w >> 1;
    const int dhalf = w & 1;
    const int myrow = b * QQ + qt * ROWS + drow;
    float* wr = W + (size_t)myrow * KKEYS;
    const float invs = 1.0f / ssum[drow];
    float* msw  = ssw[drow][dhalf];
    int*   midx = ssidx[drow][dhalf];

    int base = 0;
#pragma unroll 4
    for (int i = 0; i < 8; i++) {          // 8 float4-iters over 1024 keys
        const int f4 = dhalf * 256 + kx + 32 * i;
        float4* w4 = (float4*)wr + f4;
        float4 v = *w4;
        v.x *= invs; v.y *= invs; v.z *= invs; v.w *= invs;
        *w4 = v;
        const int k0 = f4 * 4;
        float e[4] = {v.x, v.y, v.z, v.w};
#pragma unroll
        for (int q = 0; q < 4; q++) {
            unsigned bal = __ballot_sync(0xffffffffu, e[q] > TAU);
            if (e[q] > TAU) {
                int pos = base + __popc(bal & ((1u << kx) - 1u));
                if (pos < CAPH) { msw[pos] = e[q]; midx[pos] = k0 + q; }
            }
            base += __popc(bal);
        }
    }
    if (kx == 0) {
        scnt[drow][dhalf] = base;
        if (base > CAPH) sovf[drow] = 1;
    }
    __syncthreads();

    // ---- Phase E: warp w -> row w>>1, column-half w&1 ----
    const int erow  = w >> 1;
    const int ehalf = w & 1;
    const int orow  = b * QQ + qt * ROWS + erow;
    const float* V  = vals + (size_t)b * KKEYS * VD;
    float4 acc[2];
    acc[0] = make_float4(0.f, 0.f, 0.f, 0.f);
    acc[1] = make_float4(0.f, 0.f, 0.f, 0.f);

    if (!sovf[erow]) {
#pragma unroll
        for (int hh = 0; hh < 2; hh++) {
            const int   cnt = scnt[erow][hh];
            const float* lw = ssw[erow][hh];
            const int*   li = ssidx[erow][hh];
            for (int s = 0; s < cnt; s++) {
                float wgt = lw[s];
                const float4* vr = (const float4*)(V + (size_t)li[s] * VD)
                                   + ehalf * 64;
#pragma unroll
                for (int jj = 0; jj < 2; jj++) {
                    float4 v = vr[kx + 32 * jj];
                    acc[jj].x = fmaf(wgt, v.x, acc[jj].x);
                    acc[jj].y = fmaf(wgt, v.y, acc[jj].y);
                    acc[jj].z = fmaf(wgt, v.z, acc[jj].z);
                    acc[jj].w = fmaf(wgt, v.w, acc[jj].w);
                }
            }
        }
    } else {
        // dense fallback (correctness guard; not expected with random data)
        const float* wrr = W + (size_t)orow * KKEYS;
        for (int k = 0; k < KKEYS; k++) {
            float wgt = wrr[k];
            if (wgt > TAU) {
                const float4* vr = (const float4*)(V + (size_t)k * VD)
                                   + ehalf * 64;
#pragma unroll
                for (int jj = 0; jj < 2; jj++) {
                    float4 v = vr[kx + 32 * jj];
                    acc[jj].x = fmaf(wgt, v.x, acc[jj].x);
                    acc[jj].y = fmaf(wgt, v.y, acc[jj].y);
                    acc[jj].z = fmaf(wgt, v.z, acc[jj].z);
                    acc[jj].w = fmaf(wgt, v.w, acc[jj].w);
                }
            }
        }
    }

    float4* o4 = (float4*)(Out + (size_t)orow * VD) + ehalf * 64;
    o4[kx]      = acc[0];
    o4[kx + 32] = acc[1];
}

// ---------------------------------------------------------------------------
// Launch: out layout = [output (B,Q,V) | weights (B,Q,K)] per reference tuple.
// ---------------------------------------------------------------------------
extern "C" void kernel_launch(void* const* d_in, const int* in_sizes, int n_in,
                              void* d_out, int out_size)
{
    (void)in_sizes; (void)n_in; (void)out_size;
    const float* qb   = (const float*)d_in[0];
    const float* kb   = (const float*)d_in[1];
    const float* vals = (const float*)d_in[2];
    const int*   mask = (const int*)d_in[3];

    float* out = (float*)d_out;
    float* W   = out + (size_t)BB * QQ * VD;   // weights region

    fused_kernel<<<BB * (QQ / ROWS), 256>>>(qb, kb, vals, mask, out, W);
}

// round 10
// speedup vs baseline: 1.0830x; 1.0830x over previous
#include <cuda_runtime.h>
#include <cstdint>

#define BB 4
#define QQ 1024
#define KKEYS 2048
#define NB 16
#define VD 512
#define CHUNK 256
#define NCHUNK 8
#define ROWS 8            // 4 packed row-pairs; each warp serves 2 pairs
#define CAP 128
#define TAU 2e-7f

typedef unsigned long long ull;
#define SGN2   0x8000000080000000ULL
#define ONES2  0x3F8000003F800000ULL
#define SC2    0x4380000043800000ULL   // (256.0f, 256.0f) exact 2^8 scale
#define KSTR   18                      // key stride in ulls: even (16B align), pad -> no conflicts

static __device__ __forceinline__ ull pk2(float a, float b) {
    ull r; asm("mov.b64 %0,{%1,%2};" : "=l"(r) : "f"(a), "f"(b)); return r;
}
static __device__ __forceinline__ void upk2(ull v, float& a, float& b) {
    asm("mov.b64 {%0,%1},%2;" : "=f"(a), "=f"(b) : "l"(v));
}
static __device__ __forceinline__ ull add2(ull a, ull b) {
    ull r; asm("add.rn.f32x2 %0,%1,%2;" : "=l"(r) : "l"(a), "l"(b)); return r;
}
static __device__ __forceinline__ ull mul2(ull a, ull b) {
    ull r; asm("mul.rn.f32x2 %0,%1,%2;" : "=l"(r) : "l"(a), "l"(b)); return r;
}

// ---------------------------------------------------------------------------
// Fused, max-free. R8 topology (8 rows/block, 256 thr, grid 512) with a
// slimmer inner loop: keys pre-packed in smem as (k,k) f32x2 pairs (no MOVs),
// and each warp evaluates TWO packed row-pairs (4 rows) per key load.
// Warp map Phase A: pg = w>>2 (pair-group: rows 4pg..4pg+3), h = w&3 (key
// quarter, 64 keys/chunk, j=2).
// ---------------------------------------------------------------------------
__global__ void __launch_bounds__(256, 4) fused_kernel(
    const float* __restrict__ qbits,
    const float* __restrict__ kbits,
    const float* __restrict__ vals,
    const int*   __restrict__ mask,
    float*       __restrict__ Out,
    float*       __restrict__ W)
{
    __shared__ ull   skeyp[CHUNK * KSTR];  // pre-packed (k,k) key bits
    __shared__ int   smask[CHUNK];
    __shared__ ull   sqn[4][NB];           // packed negated q bits per pair
    __shared__ float ssum[ROWS];
    __shared__ float ssw[ROWS][CAP];
    __shared__ int   ssidx[ROWS][CAP];

    const int tid = threadIdx.x;
    const int w   = tid >> 5;              // warp 0..7
    const int kx  = tid & 31;
    const int pg  = w >> 2;                // pair-group 0..1 (rows 4pg..4pg+3)
    const int h   = w & 3;                 // key quarter
    const int b   = blockIdx.x >> 7;       // 128 blocks per batch
    const int qt  = blockIdx.x & 127;
    const int rowbase = b * QQ + qt * ROWS;

    if (tid < ROWS) ssum[tid] = 0.0f;
    if (tid < 4 * NB) {                    // packed negated query bits
        int pp = tid >> 4, bit = tid & 15;
        int rA = rowbase + 2 * pp;
        float qa = qbits[(size_t)rA * NB + bit];
        float qc = qbits[(size_t)(rA + 1) * NB + bit];
        sqn[pp][bit] = pk2(-qa, -qc);
    }

    // 4 row pointers for this warp's pair-group
    float* wr0 = W + (size_t)(rowbase + 4 * pg + 0) * KKEYS;
    float* wr1 = W + (size_t)(rowbase + 4 * pg + 1) * KKEYS;
    float* wr2 = W + (size_t)(rowbase + 4 * pg + 2) * KKEYS;
    float* wr3 = W + (size_t)(rowbase + 4 * pg + 3) * KKEYS;
    const float4* kbase4 = (const float4*)(kbits + (size_t)b * KKEYS * NB);
    const int*    mbase  = mask + b * KKEYS;

    // ---- Phase A ----
    ull s20 = 0ULL, s21 = 0ULL;            // packed sums for pair0 / pair1
    for (int c = 0; c < NCHUNK; c++) {
        // stage: read 1024 float4 (256 keys x 16 bits), write packed (k,k)
#pragma unroll
        for (int it = 0; it < 4; it++) {
            int i = tid + it * 256;
            int k = i >> 2, jj = i & 3;
            float4 v = kbase4[(size_t)(c * CHUNK + k) * 4 + jj];
            ull* dst = &skeyp[k * KSTR + jj * 4];
            ((ulonglong2*)dst)[0] = make_ulonglong2(pk2(v.x, v.x), pk2(v.y, v.y));
            ((ulonglong2*)dst)[1] = make_ulonglong2(pk2(v.z, v.z), pk2(v.w, v.w));
        }
        if (tid < CHUNK) smask[tid] = mbase[c * CHUNK + tid];
        __syncthreads();

        ull prod[2][2];                    // [pair][j]
#pragma unroll 1
        for (int g = 0; g < 4; g++) {
            ull qa0 = sqn[2 * pg + 0][g * 4 + 0], qa1 = sqn[2 * pg + 0][g * 4 + 1];
            ull qa2 = sqn[2 * pg + 0][g * 4 + 2], qa3 = sqn[2 * pg + 0][g * 4 + 3];
            ull qb0 = sqn[2 * pg + 1][g * 4 + 0], qb1 = sqn[2 * pg + 1][g * 4 + 1];
            ull qb2 = sqn[2 * pg + 1][g * 4 + 2], qb3 = sqn[2 * pg + 1][g * 4 + 3];
#pragma unroll
            for (int j = 0; j < 2; j++) {
                const int kl = h * 64 + j * 32 + kx;
                const ull* kp = &skeyp[kl * KSTR + g * 4];
                ulonglong2 kv01 = ((const ulonglong2*)kp)[0];
                ulonglong2 kv23 = ((const ulonglong2*)kp)[1];
                // pair 0:  t = 1 + ((k - q) | signbit)
                {
                    ull t0 = add2(ONES2, add2(qa0, kv01.x) | SGN2);
                    ull t1 = add2(ONES2, add2(qa1, kv01.y) | SGN2);
                    ull t2 = add2(ONES2, add2(qa2, kv23.x) | SGN2);
                    ull t3 = add2(ONES2, add2(qa3, kv23.y) | SGN2);
                    ull m  = mul2(mul2(t0, t1), mul2(t2, t3));
                    prod[0][j] = (g == 0) ? m : mul2(prod[0][j], m);
                }
                // pair 1
                {
                    ull t0 = add2(ONES2, add2(qb0, kv01.x) | SGN2);
                    ull t1 = add2(ONES2, add2(qb1, kv01.y) | SGN2);
                    ull t2 = add2(ONES2, add2(qb2, kv23.x) | SGN2);
                    ull t3 = add2(ONES2, add2(qb3, kv23.y) | SGN2);
                    ull m  = mul2(mul2(t0, t1), mul2(t2, t3));
                    prod[1][j] = (g == 0) ? m : mul2(prod[1][j], m);
                }
            }
        }
        // epilogue: r10 = (256 p)^10, mask, store 4 rows, accumulate sums
#pragma unroll
        for (int j = 0; j < 2; j++) {
            const int kl = h * 64 + j * 32 + kx;
            const int kg = c * CHUNK + kl;
            const int mk = smask[kl];
#pragma unroll
            for (int pp = 0; pp < 2; pp++) {
                ull r   = mul2(prod[pp][j], SC2);
                ull r2  = mul2(r, r);
                ull r4  = mul2(r2, r2);
                ull r8  = mul2(r4, r4);
                ull r10 = mul2(r8, r2);
                float ra, rb; upk2(r10, ra, rb);
                if (mk == 0) { ra = 0.0f; rb = 0.0f; }
                if (pp == 0) { wr0[kg] = ra; wr1[kg] = rb; s20 = add2(s20, pk2(ra, rb)); }
                else         { wr2[kg] = ra; wr3[kg] = rb; s21 = add2(s21, pk2(ra, rb)); }
            }
        }
        __syncthreads();
    }

    // ---- reduce sums: 4 rows per warp; 4 warps per pair-group via atomics ----
    float s0, s1, s2f, s3;
    upk2(s20, s0, s1);
    upk2(s21, s2f, s3);
#pragma unroll
    for (int off = 16; off; off >>= 1) {
        s0  += __shfl_xor_sync(0xffffffffu, s0,  off);
        s1  += __shfl_xor_sync(0xffffffffu, s1,  off);
        s2f += __shfl_xor_sync(0xffffffffu, s2f, off);
        s3  += __shfl_xor_sync(0xffffffffu, s3,  off);
    }
    if (kx == 0) {
        atomicAdd(&ssum[4 * pg + 0], s0);
        atomicAdd(&ssum[4 * pg + 1], s1);
        atomicAdd(&ssum[4 * pg + 2], s2f);
        atomicAdd(&ssum[4 * pg + 3], s3);
    }
    __syncthreads();

    // ---- Phase D: warp w owns row w; normalize in place + ballot compact ----
    const int myrow = rowbase + w;
    float* wr = W + (size_t)myrow * KKEYS;
    const float invs = 1.0f / ssum[w];
    float* msw  = ssw[w];
    int*   midx = ssidx[w];

    int base = 0;
#pragma unroll 4
    for (int i = 0; i < KKEYS / 128; i++) {
        float4* w4 = (float4*)wr + kx + 32 * i;
        float4 v = *w4;
        v.x *= invs; v.y *= invs; v.z *= invs; v.w *= invs;
        *w4 = v;
        const int k0 = (kx + 32 * i) * 4;
        float e[4] = {v.x, v.y, v.z, v.w};
#pragma unroll
        for (int q = 0; q < 4; q++) {
            unsigned bal = __ballot_sync(0xffffffffu, e[q] > TAU);
            if (e[q] > TAU) {
                int pos = base + __popc(bal & ((1u << kx) - 1u));
                if (pos < CAP) { msw[pos] = e[q]; midx[pos] = k0 + q; }
            }
            base += __popc(bal);
        }
    }
    __syncwarp();

    // ---- Phase E: sparse GEMV ----
    const float* V = vals + (size_t)b * KKEYS * VD;
    float4 acc[4];
#pragma unroll
    for (int jj = 0; jj < 4; jj++) acc[jj] = make_float4(0.f, 0.f, 0.f, 0.f);

    if (base <= CAP) {
        for (int s = 0; s < base; s++) {
            float wgt = msw[s];
            const float4* vr = (const float4*)(V + (size_t)midx[s] * VD);
#pragma unroll
            for (int jj = 0; jj < 4; jj++) {
                float4 v = vr[kx + 32 * jj];
                acc[jj].x = fmaf(wgt, v.x, acc[jj].x);
                acc[jj].y = fmaf(wgt, v.y, acc[jj].y);
                acc[jj].z = fmaf(wgt, v.z, acc[jj].z);
                acc[jj].w = fmaf(wgt, v.w, acc[jj].w);
            }
        }
    } else {
        // correctness guard; not expected with random data
        for (int k = 0; k < KKEYS; k++) {
            float wgt = wr[k];
            if (wgt > TAU) {
                const float4* vr = (const float4*)(V + (size_t)k * VD);
#pragma unroll
                for (int jj = 0; jj < 4; jj++) {
                    float4 v = vr[kx + 32 * jj];
                    acc[jj].x = fmaf(wgt, v.x, acc[jj].x);
                    acc[jj].y = fmaf(wgt, v.y, acc[jj].y);
                    acc[jj].z = fmaf(wgt, v.z, acc[jj].z);
                    acc[jj].w = fmaf(wgt, v.w, acc[jj].w);
                }
            }
        }
    }

    float4* o4 = (float4*)(Out + (size_t)myrow * VD);
#pragma unroll
    for (int jj = 0; jj < 4; jj++) o4[kx + 32 * jj] = acc[jj];
}

// ---------------------------------------------------------------------------
// Launch: out layout = [output (B,Q,V) | weights (B,Q,K)] per reference tuple.
// ---------------------------------------------------------------------------
extern "C" void kernel_launch(void* const* d_in, const int* in_sizes, int n_in,
                              void* d_out, int out_size)
{
    (void)in_sizes; (void)n_in; (void)out_size;
    const float* qb   = (const float*)d_in[0];
    const float* kb   = (const float*)d_in[1];
    const float* vals = (const float*)d_in[2];
    const int*   mask = (const int*)d_in[3];

    float* out = (float*)d_out;
    float* W   = out + (size_t)BB * QQ * VD;   // weights region

    fused_kernel<<<BB * (QQ / ROWS), 256>>>(qb, kb, vals, mask, out, W);
}

// round 12
// speedup vs baseline: 1.1029x; 1.0183x over previous
#include <cuda_runtime.h>
#include <cstdint>

#define BB 4
#define QQ 1024
#define KKEYS 2048
#define NB 16
#define VD 512
#define CHUNK 256
#define NCHUNK 8
#define ROWS 8            // per block: 4 packed row-pairs, 2 warps per pair
#define CAP 128
#define TAU 2e-7f

typedef unsigned long long ull;
#define SGN2   0x8000000080000000ULL
#define ONES2  0x3F8000003F800000ULL
#define SC2    0x4380000043800000ULL   // (256.0f, 256.0f) exact 2^8 scale

static __device__ __forceinline__ ull pk2(float a, float b) {
    ull r; asm("mov.b64 %0,{%1,%2};" : "=l"(r) : "f"(a), "f"(b)); return r;
}
static __device__ __forceinline__ void upk2(ull v, float& a, float& b) {
    asm("mov.b64 {%0,%1},%2;" : "=f"(a), "=f"(b) : "l"(v));
}
static __device__ __forceinline__ ull add2(ull a, ull b) {
    ull r; asm("add.rn.f32x2 %0,%1,%2;" : "=l"(r) : "l"(a), "l"(b)); return r;
}
static __device__ __forceinline__ ull mul2(ull a, ull b) {
    ull r; asm("mul.rn.f32x2 %0,%1,%2;" : "=l"(r) : "l"(a), "l"(b)); return r;
}

#define CP_ASYNC16(dst_u32, src) \
    asm volatile("cp.async.cg.shared.global [%0], [%1], 16;" :: "r"(dst_u32), "l"(src))
#define CP_ASYNC4(dst_u32, src) \
    asm volatile("cp.async.ca.shared.global [%0], [%1], 4;" :: "r"(dst_u32), "l"(src))
#define CP_COMMIT()  asm volatile("cp.async.commit_group;")
#define CP_WAIT0()   asm volatile("cp.async.wait_group 0;" ::: "memory")

// Dynamic smem layout (bytes, 16B-aligned segments):
//   skey  : 2 * CHUNK*20 floats = 40960
//   smask : 2 * CHUNK ints      = 2048
//   sqn   : 4 * NB ulls         = 512
//   ssum  : ROWS floats          = 32  (+pad 16B)
//   ssw   : ROWS*CAP floats      = 4096
//   ssidx : ROWS*CAP ints        = 4096
// total 51760 B -> 4 blocks/SM (207KB < 227KB)
#define SMEM_BYTES 51760

__global__ void __launch_bounds__(256, 4) fused_kernel(
    const float* __restrict__ qbits,
    const float* __restrict__ kbits,
    const float* __restrict__ vals,
    const int*   __restrict__ mask,
    float*       __restrict__ Out,
    float*       __restrict__ W)
{
    extern __shared__ float dsm[];
    float* skey0 = dsm;                        // CHUNK*20
    float* skey1 = skey0 + CHUNK * 20;         // CHUNK*20
    int*   smask0 = (int*)(skey1 + CHUNK * 20);
    int*   smask1 = smask0 + CHUNK;
    ull*   sqn   = (ull*)(smask1 + CHUNK);     // [4][NB]
    float* ssum  = (float*)(sqn + 4 * NB);     // ROWS (+ pad to 16B)
    float* ssw   = ssum + ROWS + 4;            // [ROWS][CAP]
    int*   ssidx = (int*)(ssw + ROWS * CAP);   // [ROWS][CAP]

    float* skeyb[2]  = {skey0, skey1};
    int*   smaskb[2] = {smask0, smask1};

    const int tid = threadIdx.x;
    const int w   = tid >> 5;               // warp 0..7
    const int kx  = tid & 31;
    const int p   = w >> 1;                 // row-pair 0..3
    const int h   = w & 1;                  // key half within chunk
    const int b   = blockIdx.x >> 7;        // 128 blocks per batch
    const int qt  = blockIdx.x & 127;
    const int rowbase = b * QQ + qt * ROWS;
    const int rowA = rowbase + 2 * p;
    const int rowB = rowA + 1;

    if (tid < ROWS) ssum[tid] = 0.0f;
    if (tid < 4 * NB) {                     // packed negated query bits
        int pp = tid >> 4, bit = tid & 15;
        int rA = rowbase + 2 * pp;
        float qa = qbits[(size_t)rA * NB + bit];
        float qc = qbits[(size_t)(rA + 1) * NB + bit];
        sqn[pp * NB + bit] = pk2(-qa, -qc);
    }

    float* wrA = W + (size_t)rowA * KKEYS;
    float* wrB = W + (size_t)rowB * KKEYS;
    const float4* kbase4 = (const float4*)(kbits + (size_t)b * KKEYS * NB);
    const int*    mbase  = mask + b * KKEYS;

    const int sk = tid >> 2, sj = tid & 3;  // fixed (key, quarter) per thread
    auto stage = [&](int c, int bf) {
#pragma unroll
        for (int it = 0; it < 4; it++) {
            int k = sk + it * 64;
            uint32_t dst = (uint32_t)__cvta_generic_to_shared(
                &skeyb[bf][k * 20 + sj * 4]);
            CP_ASYNC16(dst, (const void*)&kbase4[(size_t)(c * CHUNK + k) * 4 + sj]);
        }
        uint32_t dm = (uint32_t)__cvta_generic_to_shared(&smaskb[bf][tid]);
        CP_ASYNC4(dm, (const void*)&mbase[c * CHUNK + tid]);
    };

    // ---- Phase A: pipelined chunks ----
    stage(0, 0);
    CP_COMMIT();

    ull s2 = 0ULL;
    for (int c = 0; c < NCHUNK; c++) {
        const int bf = c & 1;
        const float* skc = skeyb[bf];
        const int*   smc = smaskb[bf];
        CP_WAIT0();
        __syncthreads();                    // buf[bf] staged; prev compute done
        if (c + 1 < NCHUNK) {
            stage(c + 1, bf ^ 1);
            CP_COMMIT();
        }

        ull prod[4];
#pragma unroll 1
        for (int g = 0; g < 4; g++) {       // bit-group outer: few live q-regs
            const ull q0 = sqn[p * NB + g * 4 + 0];
            const ull q1 = sqn[p * NB + g * 4 + 1];
            const ull q2 = sqn[p * NB + g * 4 + 2];
            const ull q3 = sqn[p * NB + g * 4 + 3];
#pragma unroll
            for (int j = 0; j < 4; j++) {
                const int kl = h * 128 + j * 32 + kx;
                float4 kv = *(const float4*)&skc[kl * 20 + g * 4];
                // t = 1 - |q-k| = 1 + ((k-q) | signbit)
                ull t0 = add2(ONES2, add2(q0, pk2(kv.x, kv.x)) | SGN2);
                ull t1 = add2(ONES2, add2(q1, pk2(kv.y, kv.y)) | SGN2);
                ull t2 = add2(ONES2, add2(q2, pk2(kv.z, kv.z)) | SGN2);
                ull t3 = add2(ONES2, add2(q3, pk2(kv.w, kv.w)) | SGN2);
                ull m  = mul2(mul2(t0, t1), mul2(t2, t3));
                prod[j] = (g == 0) ? m : mul2(prod[j], m);
            }
        }
#pragma unroll
        for (int j = 0; j < 4; j++) {
            const int kl = h * 128 + j * 32 + kx;
            // r10 = (256*p)^10  (exact 2^80 scale; max-free normalization)
            ull r   = mul2(prod[j], SC2);
            ull r2  = mul2(r, r);
            ull r4  = mul2(r2, r2);
            ull r8  = mul2(r4, r4);
            ull r10 = mul2(r8, r2);
            float ra, rb; upk2(r10, ra, rb);
            if (smc[kl] == 0) { ra = 0.0f; rb = 0.0f; }
            const int kg = c * CHUNK + kl;
            wrA[kg] = ra;
            wrB[kg] = rb;
            s2 = add2(s2, pk2(ra, rb));
        }
        __syncthreads();                    // compute(c) done before buf reuse
    }

    // ---- reduce sums ----
    float sA, sB; upk2(s2, sA, sB);
#pragma unroll
    for (int off = 16; off; off >>= 1) {
        sA += __shfl_xor_sync(0xffffffffu, sA, off);
        sB += __shfl_xor_sync(0xffffffffu, sB, off);
    }
    if (kx == 0) {
        atomicAdd(&ssum[2 * p],     sA);
        atomicAdd(&ssum[2 * p + 1], sB);
    }
    __syncthreads();

    // ---- Phase D: warp w owns row w; normalize in place + ballot compact ----
    const int myrow = rowbase + w;
    float* wr = W + (size_t)myrow * KKEYS;
    const float invs = 1.0f / ssum[w];
    float* msw  = ssw + w * CAP;
    int*   midx = ssidx + w * CAP;

    int base = 0;
#pragma unroll 4
    for (int i = 0; i < KKEYS / 128; i++) {
        float4* w4 = (float4*)wr + kx + 32 * i;
        float4 v = *w4;
        v.x *= invs; v.y *= invs; v.z *= invs; v.w *= invs;
        *w4 = v;
        const int k0 = (kx + 32 * i) * 4;
        float e[4] = {v.x, v.y, v.z, v.w};
#pragma unroll
        for (int q = 0; q < 4; q++) {
            unsigned bal = __ballot_sync(0xffffffffu, e[q] > TAU);
            if (e[q] > TAU) {
                int pos = base + __popc(bal & ((1u << kx) - 1u));
                if (pos < CAP) { msw[pos] = e[q]; midx[pos] = k0 + q; }
            }
            base += __popc(bal);
        }
    }
    __syncwarp();

    // ---- Phase E: sparse GEMV ----
    const float* V = vals + (size_t)b * KKEYS * VD;
    float4 acc[4];
#pragma unroll
    for (int jj = 0; jj < 4; jj++) acc[jj] = make_float4(0.f, 0.f, 0.f, 0.f);

    if (base <= CAP) {
        for (int s = 0; s < base; s++) {
            float wgt = msw[s];
            const float4* vr = (const float4*)(V + (size_t)midx[s] * VD);
#pragma unroll
            for (int jj = 0; jj < 4; jj++) {
                float4 v = vr[kx + 32 * jj];
                acc[jj].x = fmaf(wgt, v.x, acc[jj].x);
                acc[jj].y = fmaf(wgt, v.y, acc[jj].y);
                acc[jj].z = fmaf(wgt, v.z, acc[jj].z);
                acc[jj].w = fmaf(wgt, v.w, acc[jj].w);
            }
        }
    } else {
        // correctness guard; not expected with random data
        for (int k = 0; k < KKEYS; k++) {
            float wgt = wr[k];
            if (wgt > TAU) {
                const float4* vr = (const float4*)(V + (size_t)k * VD);
#pragma unroll
                for (int jj = 0; jj < 4; jj++) {
                    float4 v = vr[kx + 32 * jj];
                    acc[jj].x = fmaf(wgt, v.x, acc[jj].x);
                    acc[jj].y = fmaf(wgt, v.y, acc[jj].y);
                    acc[jj].z = fmaf(wgt, v.z, acc[jj].z);
                    acc[jj].w = fmaf(wgt, v.w, acc[jj].w);
                }
            }
        }
    }

    float4* o4 = (float4*)(Out + (size_t)myrow * VD);
#pragma unroll
    for (int jj = 0; jj < 4; jj++) o4[kx + 32 * jj] = acc[jj];
}

// ---------------------------------------------------------------------------
// Launch: out layout = [output (B,Q,V) | weights (B,Q,K)] per reference tuple.
// ---------------------------------------------------------------------------
extern "C" void kernel_launch(void* const* d_in, const int* in_sizes, int n_in,
                              void* d_out, int out_size)
{
    (void)in_sizes; (void)n_in; (void)out_size;
    const float* qb   = (const float*)d_in[0];
    const float* kb   = (const float*)d_in[1];
    const float* vals = (const float*)d_in[2];
    const int*   mask = (const int*)d_in[3];

    float* out = (float*)d_out;
    float* W   = out + (size_t)BB * QQ * VD;   // weights region

    cudaFuncSetAttribute(fused_kernel,
                         cudaFuncAttributeMaxDynamicSharedMemorySize, SMEM_BYTES);
    fused_kernel<<<BB * (QQ / ROWS), 256, SMEM_BYTES>>>(qb, kb, vals, mask, out, W);
}

// round 13
// speedup vs baseline: 1.1617x; 1.0533x over previous
#include <cuda_runtime.h>
#include <cstdint>

#define BB 4
#define QQ 1024
#define KKEYS 2048
#define NB 16
#define VD 512
#define CHUNK 256
#define ROWS 8            // rows per K1 block: 4 packed row-pairs
#define KHALF 1024        // keys per K1 block
#define NCH   (KHALF / CHUNK)   // 4 chunks per K1 block
#define CAP 256
#define TAU 2e-7f

typedef unsigned long long ull;
#define SGN2   0x8000000080000000ULL
#define ONES2  0x3F8000003F800000ULL
#define SC2    0x4380000043800000ULL   // (256.0f, 256.0f) exact 2^8 scale

static __device__ __forceinline__ ull pk2(float a, float b) {
    ull r; asm("mov.b64 %0,{%1,%2};" : "=l"(r) : "f"(a), "f"(b)); return r;
}
static __device__ __forceinline__ void upk2(ull v, float& a, float& b) {
    asm("mov.b64 {%0,%1},%2;" : "=f"(a), "=f"(b) : "l"(v));
}
static __device__ __forceinline__ ull add2(ull a, ull b) {
    ull r; asm("add.rn.f32x2 %0,%1,%2;" : "=l"(r) : "l"(a), "l"(b)); return r;
}
static __device__ __forceinline__ ull mul2(ull a, ull b) {
    ull r; asm("mul.rn.f32x2 %0,%1,%2;" : "=l"(r) : "l"(a), "l"(b)); return r;
}

// ---------------------------------------------------------------------------
// K1: pure producer. Block = 8 rows x 1024 keys; grid 1024 (key-split, no
// duplicated staging). Writes raw r10 = (256 p)^10 into W. No reductions.
// Warp map: p = w>>1 (row-pair), h = w&1 (128-key half of each 256 chunk).
// ---------------------------------------------------------------------------
__global__ void __launch_bounds__(256, 4) prod10_kernel(
    const float* __restrict__ qbits,
    const float* __restrict__ kbits,
    const int*   __restrict__ mask,
    float*       __restrict__ W)
{
    __shared__ float skey[CHUNK * 20];     // pad 20 -> conflict-free LDS.128
    __shared__ int   smask[CHUNK];
    __shared__ ull   sqn[4][NB];           // packed negated q bits per pair

    const int tid = threadIdx.x;
    const int w   = tid >> 5;              // warp 0..7
    const int kx  = tid & 31;
    const int p   = w >> 1;                // row-pair 0..3
    const int h   = w & 1;                 // key half within chunk
    const int bid = blockIdx.x;
    const int kh  = bid & 1;               // key half of the row (0..1)
    const int qt  = (bid >> 1) & 127;
    const int b   = bid >> 8;
    const int rowbase = b * QQ + qt * ROWS;
    const int rowA = rowbase + 2 * p;
    const int rowB = rowA + 1;

    if (tid < 4 * NB) {                    // packed negated query bits
        int pp = tid >> 4, bit = tid & 15;
        int rA = rowbase + 2 * pp;
        float qa = qbits[(size_t)rA * NB + bit];
        float qc = qbits[(size_t)(rA + 1) * NB + bit];
        sqn[pp][bit] = pk2(-qa, -qc);
    }

    float* wrA = W + (size_t)rowA * KKEYS;
    float* wrB = W + (size_t)rowB * KKEYS;
    const float4* kbase4 = (const float4*)(kbits + (size_t)b * KKEYS * NB);
    const int*    mbase  = mask + b * KKEYS;

    for (int c = 0; c < NCH; c++) {
        const int cg = kh * NCH + c;       // global chunk 0..7
#pragma unroll
        for (int it = 0; it < 4; it++) {   // stage 256 keys x 16 floats
            int i = tid + it * 256;
            int k = i >> 2, j = i & 3;
            float4 v = kbase4[(size_t)(cg * CHUNK + k) * 4 + j];
            *(float4*)&skey[k * 20 + j * 4] = v;
        }
        if (tid < CHUNK) smask[tid] = mbase[cg * CHUNK + tid];
        __syncthreads();

        ull prod[4];
#pragma unroll 1
        for (int g = 0; g < 4; g++) {      // bit-group outer: few live q-regs
            const ull q0 = sqn[p][g * 4 + 0];
            const ull q1 = sqn[p][g * 4 + 1];
            const ull q2 = sqn[p][g * 4 + 2];
            const ull q3 = sqn[p][g * 4 + 3];
#pragma unroll
            for (int j = 0; j < 4; j++) {
                const int kl = h * 128 + j * 32 + kx;
                float4 kv = *(const float4*)&skey[kl * 20 + g * 4];
                // t = 1 - |q-k| = 1 + ((k-q) | signbit)
                ull t0 = add2(ONES2, add2(q0, pk2(kv.x, kv.x)) | SGN2);
                ull t1 = add2(ONES2, add2(q1, pk2(kv.y, kv.y)) | SGN2);
                ull t2 = add2(ONES2, add2(q2, pk2(kv.z, kv.z)) | SGN2);
                ull t3 = add2(ONES2, add2(q3, pk2(kv.w, kv.w)) | SGN2);
                ull m  = mul2(mul2(t0, t1), mul2(t2, t3));
                prod[j] = (g == 0) ? m : mul2(prod[j], m);
            }
        }
#pragma unroll
        for (int j = 0; j < 4; j++) {
            const int kl = h * 128 + j * 32 + kx;
            // r10 = (256*p)^10  (exact 2^80 scale; max-free normalization)
            ull r   = mul2(prod[j], SC2);
            ull r2  = mul2(r, r);
            ull r4  = mul2(r2, r2);
            ull r8  = mul2(r4, r4);
            ull r10 = mul2(r8, r2);
            float ra, rb; upk2(r10, ra, rb);
            if (smask[kl] == 0) { ra = 0.0f; rb = 0.0f; }
            const int kg = cg * CHUNK + kl;
            wrA[kg] = ra;
            wrB[kg] = rb;
        }
        __syncthreads();
    }
}

// ---------------------------------------------------------------------------
// K2: consumer. One block per row (grid 4096, 256 thr, tiny smem -> high occ).
// Reads the row (needed for normalization anyway -> no global-sum handoff),
// block-reduces the sum, normalizes + writes W, compacts significant keys
// (smem atomic; S~7), then sparse GEMV with float2 per thread.
// ---------------------------------------------------------------------------
__global__ void __launch_bounds__(256, 8) norm_gemv_kernel(
    float*       __restrict__ W,
    const float* __restrict__ vals,
    float*       __restrict__ Out)
{
    __shared__ float red[8];
    __shared__ float s_inv;
    __shared__ float sw[CAP];
    __shared__ int   sidx[CAP];
    __shared__ int   scnt;

    const int row = blockIdx.x;
    const int b   = row >> 10;
    const int tid = threadIdx.x;
    float4* wr4 = (float4*)(W + (size_t)row * KKEYS);

    if (tid == 0) scnt = 0;

    // read 2 float4 per thread (512 float4 = 2048 floats)
    float4 v0 = wr4[tid];
    float4 v1 = wr4[tid + 256];
    float lsum = (v0.x + v0.y) + (v0.z + v0.w)
               + (v1.x + v1.y) + (v1.z + v1.w);
#pragma unroll
    for (int off = 16; off; off >>= 1)
        lsum += __shfl_xor_sync(0xffffffffu, lsum, off);
    if ((tid & 31) == 0) red[tid >> 5] = lsum;
    __syncthreads();
    if (tid < 32) {
        float v = (tid < 8) ? red[tid] : 0.0f;
#pragma unroll
        for (int off = 4; off; off >>= 1)
            v += __shfl_xor_sync(0xffffffffu, v, off);
        if (tid == 0) s_inv = 1.0f / v;
    }
    __syncthreads();
    const float invs = s_inv;

    // normalize + write back + compact (S ~ 7 -> few atomics)
    v0.x *= invs; v0.y *= invs; v0.z *= invs; v0.w *= invs;
    v1.x *= invs; v1.y *= invs; v1.z *= invs; v1.w *= invs;
    wr4[tid]       = v0;
    wr4[tid + 256] = v1;
    {
        float e[8] = {v0.x, v0.y, v0.z, v0.w, v1.x, v1.y, v1.z, v1.w};
#pragma unroll
        for (int q = 0; q < 8; q++) {
            if (e[q] > TAU) {
                int pos = atomicAdd(&scnt, 1);
                int k = (q < 4) ? (tid * 4 + q) : ((tid + 256) * 4 + q - 4);
                if (pos < CAP) { sw[pos] = e[q]; sidx[pos] = k; }
            }
        }
    }
    __syncthreads();

    const int S = scnt;
    const float* V = vals + (size_t)b * KKEYS * VD;
    float ax = 0.0f, ay = 0.0f;
    if (S <= CAP) {
        for (int s = 0; s < S; s++) {
            float wgt = sw[s];
            const float2 v = ((const float2*)(V + (size_t)sidx[s] * VD))[tid];
            ax = fmaf(wgt, v.x, ax);
            ay = fmaf(wgt, v.y, ay);
        }
    } else {
        // dense fallback (correctness guard; W row already normalized+synced)
        const float* wr = W + (size_t)row * KKEYS;
        for (int k = 0; k < KKEYS; k++) {
            float wgt = wr[k];
            if (wgt > TAU) {
                const float2 v = ((const float2*)(V + (size_t)k * VD))[tid];
                ax = fmaf(wgt, v.x, ax);
                ay = fmaf(wgt, v.y, ay);
            }
        }
    }
    ((float2*)(Out + (size_t)row * VD))[tid] = make_float2(ax, ay);
}

// ---------------------------------------------------------------------------
// Launch: out layout = [output (B,Q,V) | weights (B,Q,K)] per reference tuple.
// ---------------------------------------------------------------------------
extern "C" void kernel_launch(void* const* d_in, const int* in_sizes, int n_in,
                              void* d_out, int out_size)
{
    (void)in_sizes; (void)n_in; (void)out_size;
    const float* qb   = (const float*)d_in[0];
    const float* kb   = (const float*)d_in[1];
    const float* vals = (const float*)d_in[2];
    const int*   mask = (const int*)d_in[3];

    float* out = (float*)d_out;
    float* W   = out + (size_t)BB * QQ * VD;   // weights region

    prod10_kernel<<<BB * (QQ / ROWS) * 2, 256>>>(qb, kb, mask, W);
    norm_gemv_kernel<<<BB * QQ, 256>>>(W, vals, out);
}